// round 10
// baseline (speedup 1.0000x reference)
#include <cuda_runtime.h>
#include <cuda_bf16.h>
#include <cstdint>

// SANet attention, warp-level bf16 HMMA (base PTX), R8:
// pre-pass kernel converts all K/V to bf16 hi/lo tile blocks in global scratch
// (exact SMEM layout); main kernel cp.asyncs finished tiles -> loop is
// GEMM1 / softmax / GEMM2 only. Math identical to R5 (3-term bf16 split,
// no-max softmax).

namespace {
constexpr int HW  = 4096;
constexpr int BQ  = 128;
constexpr int NKT = 32;
constexpr int NT  = 512;     // 16 warps: (qblk 0..7) x (khalf 0..1)

constexpr int QK_STR = 72;   // bf16 elems per K row (144 B)
constexpr int V_STR  = 136;  // bf16 elems per V row (272 B)

constexpr int KPLANE = 128 * 144;            // 18432 B per K plane
constexpr int VPLANE = 64 * 272;             // 17408 B per V plane
constexpr int OFF_VHI = 2 * KPLANE;          // V planes after K hi/lo
constexpr int BUF_SZ  = 2 * KPLANE + 2 * VPLANE;  // 71680 B per tile block
constexpr int SMEM_BYTES = 2 * BUF_SZ;       // 143360 B (double buffer)
constexpr int KLO_E = KPLANE / 2;            // elem offset hi->lo
constexpr int VLO_E = VPLANE / 2;
constexpr int NCHUNK = BUF_SZ / 16;          // 4480 16B chunks per tile
}

__device__ __align__(16) char g_kv[(size_t)4 * NKT * BUF_SZ];   // 9.2 MB scratch

__device__ __forceinline__ uint32_t smem_u32(const void* p) {
    uint32_t a;
    asm("{ .reg .u64 t; cvta.to.shared.u64 t, %1; cvt.u32.u64 %0, t; }"
        : "=r"(a) : "l"(p));
    return a;
}
__device__ __forceinline__ void cpa16(uint32_t s, const void* g) {
    asm volatile("cp.async.cg.shared.global [%0], [%1], 16;" :: "r"(s), "l"(g));
}
__device__ __forceinline__ void cpa_commit() {
    asm volatile("cp.async.commit_group;" ::: "memory");
}
__device__ __forceinline__ void cpa_wait0() {
    asm volatile("cp.async.wait_group 0;" ::: "memory");
}
__device__ __forceinline__ void ldsm4(uint32_t a, uint32_t* r) {
    asm volatile("ldmatrix.sync.aligned.m8n8.x4.shared.b16 {%0,%1,%2,%3}, [%4];"
                 : "=r"(r[0]), "=r"(r[1]), "=r"(r[2]), "=r"(r[3]) : "r"(a));
}
__device__ __forceinline__ void mma_bf16(float* d, const uint32_t* a,
                                         const uint32_t* b) {
    asm volatile(
        "mma.sync.aligned.m16n8k16.row.col.f32.bf16.bf16.f32 "
        "{%0,%1,%2,%3}, {%4,%5,%6,%7}, {%8,%9}, {%0,%1,%2,%3};"
        : "+f"(d[0]), "+f"(d[1]), "+f"(d[2]), "+f"(d[3])
        : "r"(a[0]), "r"(a[1]), "r"(a[2]), "r"(a[3]), "r"(b[0]), "r"(b[1]));
}
__device__ __forceinline__ void split_pack(float x, float y,
                                           uint32_t& hi, uint32_t& lo) {
    __nv_bfloat16 xh = __float2bfloat16_rn(x);
    __nv_bfloat16 yh = __float2bfloat16_rn(y);
    __nv_bfloat16 xl = __float2bfloat16_rn(x - __bfloat162float(xh));
    __nv_bfloat16 yl = __float2bfloat16_rn(y - __bfloat162float(yh));
    hi = (uint32_t)__bfloat16_as_ushort(xh) |
         ((uint32_t)__bfloat16_as_ushort(yh) << 16);
    lo = (uint32_t)__bfloat16_as_ushort(xl) |
         ((uint32_t)__bfloat16_as_ushort(yl) << 16);
}

// ---------------- pre-pass: K/V fp32 -> bf16 hi/lo tile blocks ----------------
__global__ __launch_bounds__(512)
void sanet_prepass(const float* __restrict__ Ksrc, const float* __restrict__ Vsrc)
{
    const int kt = blockIdx.x, b = blockIdx.y, tid = threadIdx.x;
    char* dst = g_kv + (size_t)(b * NKT + kt) * BUF_SZ;
    const float* Kg = Ksrc + (size_t)b * 64 * HW + kt * 128;
    const float* Vg = Vsrc + (size_t)b * 64 * HW + kt * 128;

    {   // K -> [k][c] planes (transpose), 144B rows
        const int k = tid & 127, c0 = (tid >> 7) * 16;
        float f[16];
        uint32_t h[8], l[8];
        #pragma unroll
        for (int j = 0; j < 16; ++j) f[j] = Kg[(size_t)(c0 + j) * HW + k];
        #pragma unroll
        for (int j = 0; j < 8; ++j) split_pack(f[2 * j], f[2 * j + 1], h[j], l[j]);
        char* d = dst + k * 144 + c0 * 2;
        *(uint4*)(d)                = make_uint4(h[0], h[1], h[2], h[3]);
        *(uint4*)(d + 16)           = make_uint4(h[4], h[5], h[6], h[7]);
        *(uint4*)(d + KPLANE)       = make_uint4(l[0], l[1], l[2], l[3]);
        *(uint4*)(d + KPLANE + 16)  = make_uint4(l[4], l[5], l[6], l[7]);
    }
    {   // V -> [c][k] planes (no transpose), 272B rows
        const int c = tid >> 3, kq = (tid & 7) * 16;
        float f[16];
        uint32_t h[8], l[8];
        #pragma unroll
        for (int j = 0; j < 4; ++j)
            *(float4*)(f + 4 * j) = *(const float4*)(Vg + (size_t)c * HW + kq + 4 * j);
        #pragma unroll
        for (int j = 0; j < 8; ++j) split_pack(f[2 * j], f[2 * j + 1], h[j], l[j]);
        char* d = dst + OFF_VHI + c * 272 + kq * 2;
        *(uint4*)(d)                = make_uint4(h[0], h[1], h[2], h[3]);
        *(uint4*)(d + 16)           = make_uint4(h[4], h[5], h[6], h[7]);
        *(uint4*)(d + VPLANE)       = make_uint4(l[0], l[1], l[2], l[3]);
        *(uint4*)(d + VPLANE + 16)  = make_uint4(l[4], l[5], l[6], l[7]);
    }
}

// ---------------- main kernel ----------------
__global__ __launch_bounds__(NT, 1)
void sanet_main(const float* __restrict__ content, float* __restrict__ out)
{
    extern __shared__ __align__(16) char smc[];
    const uint32_t sb = smem_u32(smc);

    const int tid   = threadIdx.x;
    const int wid   = tid >> 5;
    const int lane  = tid & 31;
    const int qblk  = wid & 7;
    const int khalf = wid >> 3;
    const int g     = lane >> 2;
    const int t     = lane & 3;
    const int b     = blockIdx.y;
    const int q0    = blockIdx.x * BQ;

    const float* Qg = content + (size_t)b * 64 * HW;
    float* outg     = out     + (size_t)b * 128 * HW;
    const char* kvb = g_kv + (size_t)b * NKT * BUF_SZ;

    const uint32_t laneK = (uint32_t)(lane & 7) * 144u +
                           (uint32_t)((lane >> 3) & 1) * 16u +
                           (uint32_t)((lane >> 4) & 1) * (uint32_t)KPLANE;
    const uint32_t laneV = (uint32_t)(lane & 7) * 272u +
                           (uint32_t)((lane >> 3) & 1) * 16u +
                           (uint32_t)((lane >> 4) & 1) * (uint32_t)VPLANE;

    // ---- prologue: stage Q fp32 into buf0 area ----
    float* stQ = (float*)smc;   // [64c][128q] fp32, 32 KB (before tile 0 load)
    #pragma unroll
    for (int j = 0; j < 4; ++j) {
        const int idx = tid + 512 * j;
        const int c = idx >> 5, kc = idx & 31;
        cpa16(sb + c * 512 + kc * 16, Qg + (size_t)c * HW + q0 + kc * 4);
    }
    cpa_commit();
    cpa_wait0();
    __syncthreads();

    {   // content passthrough (coalesced)
        const int q = tid & 127;
        const int c0 = (tid >> 7) * 16;
        #pragma unroll
        for (int j = 0; j < 16; ++j)
            outg[(size_t)(c0 + j) * HW + q0 + q] = stQ[(c0 + j) * 128 + q];
    }

    // ---- persistent Q A-fragments, split in registers from fp32 stage ----
    uint32_t qa_hi[4][4], qa_lo[4][4];
    {
        const int qA = qblk * 16 + g;
        #pragma unroll
        for (int s = 0; s < 4; ++s) {
            const int ch = 16 * s + 2 * t;
            split_pack(stQ[ch * 128 + qA],           stQ[(ch + 1) * 128 + qA],
                       qa_hi[s][0], qa_lo[s][0]);
            split_pack(stQ[ch * 128 + qA + 8],       stQ[(ch + 1) * 128 + qA + 8],
                       qa_hi[s][1], qa_lo[s][1]);
            split_pack(stQ[(ch + 8) * 128 + qA],     stQ[(ch + 9) * 128 + qA],
                       qa_hi[s][2], qa_lo[s][2]);
            split_pack(stQ[(ch + 8) * 128 + qA + 8], stQ[(ch + 9) * 128 + qA + 8],
                       qa_hi[s][3], qa_lo[s][3]);
        }
    }
    __syncthreads();   // stage reads done before tile 0 overwrites buf0

    // ---- prime tile 0 ----
    for (int j = tid; j < NCHUNK; j += NT)
        cpa16(sb + j * 16, kvb + j * 16);
    cpa_commit();
    cpa_wait0();
    __syncthreads();

    float oAcc[8][4];
    #pragma unroll
    for (int nt = 0; nt < 8; ++nt)
        #pragma unroll
        for (int i = 0; i < 4; ++i) oAcc[nt][i] = 0.0f;
    float l0sum = 0.0f, l1sum = 0.0f;

    for (int kt = 0; kt < NKT; ++kt) {
        // prefetch tile kt+1 into the other buffer (overlaps the GEMMs)
        if (kt + 1 < NKT) {
            const uint32_t dst = sb + (uint32_t)((kt + 1) & 1) * BUF_SZ;
            const char* src = kvb + (size_t)(kt + 1) * BUF_SZ;
            for (int j = tid; j < NCHUNK; j += NT)
                cpa16(dst + j * 16, src + j * 16);
            cpa_commit();
        }

        const uint32_t bufb = sb + (uint32_t)(kt & 1) * BUF_SZ;
        const uint32_t kaddr = bufb + (uint32_t)khalf * (64u * 144u) + laneK;
        const uint32_t vaddr = bufb + OFF_VHI + (uint32_t)khalf * 128u + laneV;

        // ---- GEMM1: S[16q x 64k] = Q.K^T (3-term bf16 split) ----
        float sAcc[8][4];
        #pragma unroll
        for (int nt = 0; nt < 8; ++nt)
            #pragma unroll
            for (int i = 0; i < 4; ++i) sAcc[nt][i] = 0.0f;

        #pragma unroll
        for (int s = 0; s < 4; ++s) {
            #pragma unroll
            for (int np = 0; np < 4; ++np) {
                uint32_t ra[4], rb[4];
                ldsm4(kaddr + (2 * np) * 1152u + s * 32u, ra);
                ldsm4(kaddr + (2 * np + 1) * 1152u + s * 32u, rb);
                mma_bf16(sAcc[2 * np],     qa_hi[s], ra);
                mma_bf16(sAcc[2 * np + 1], qa_hi[s], rb);
                mma_bf16(sAcc[2 * np],     qa_hi[s], ra + 2);
                mma_bf16(sAcc[2 * np + 1], qa_hi[s], rb + 2);
                mma_bf16(sAcc[2 * np],     qa_lo[s], ra);
                mma_bf16(sAcc[2 * np + 1], qa_lo[s], rb);
            }
        }

        // ---- softmax (no max shift) + in-place P fragment build ----
        float* flat = &sAcc[0][0];
        float r0 = 0.0f, r1 = 0.0f;
        #pragma unroll
        for (int s = 0; s < 4; ++s) {
            float p[8];
            #pragma unroll
            for (int i = 0; i < 8; ++i) p[i] = __expf(flat[8 * s + i]);
            r0 += (p[0] + p[1]) + (p[4] + p[5]);
            r1 += (p[2] + p[3]) + (p[6] + p[7]);
            uint32_t h01, l01, h23, l23, h45, l45, h67, l67;
            split_pack(p[0], p[1], h01, l01);
            split_pack(p[2], p[3], h23, l23);
            split_pack(p[4], p[5], h45, l45);
            split_pack(p[6], p[7], h67, l67);
            flat[8 * s + 0] = __uint_as_float(h01);
            flat[8 * s + 1] = __uint_as_float(h23);
            flat[8 * s + 2] = __uint_as_float(h45);
            flat[8 * s + 3] = __uint_as_float(h67);
            flat[8 * s + 4] = __uint_as_float(l01);
            flat[8 * s + 5] = __uint_as_float(l23);
            flat[8 * s + 6] = __uint_as_float(l45);
            flat[8 * s + 7] = __uint_as_float(l67);
        }
        r0 += __shfl_xor_sync(0xffffffffu, r0, 1);
        r0 += __shfl_xor_sync(0xffffffffu, r0, 2);
        r1 += __shfl_xor_sync(0xffffffffu, r1, 1);
        r1 += __shfl_xor_sync(0xffffffffu, r1, 2);
        l0sum += r0;
        l1sum += r1;

        // ---- GEMM2: O[16q x 64c] += P.V^T (partial over this key half) ----
        #pragma unroll
        for (int s = 0; s < 4; ++s) {
            uint32_t ah[4], al[4];
            #pragma unroll
            for (int i = 0; i < 4; ++i) {
                ah[i] = __float_as_uint(flat[8 * s + i]);
                al[i] = __float_as_uint(flat[8 * s + 4 + i]);
            }
            #pragma unroll
            for (int np = 0; np < 4; ++np) {
                uint32_t ra[4], rb[4];
                ldsm4(vaddr + (2 * np) * 2176u + s * 32u, ra);
                ldsm4(vaddr + (2 * np + 1) * 2176u + s * 32u, rb);
                mma_bf16(oAcc[2 * np],     ah, ra);
                mma_bf16(oAcc[2 * np + 1], ah, rb);
                mma_bf16(oAcc[2 * np],     ah, ra + 2);
                mma_bf16(oAcc[2 * np + 1], ah, rb + 2);
                mma_bf16(oAcc[2 * np],     al, ra);
                mma_bf16(oAcc[2 * np + 1], al, rb);
            }
        }

        if (kt + 1 < NKT) cpa_wait0();
        __syncthreads();   // all reads of buf[kt&1] done; tile kt+1 visible
    }

    // ---- epilogue: pair-reduce khalf partials via SMEM, normalize, store ----
    float* redO = (float*)smc;             // 8 warps * 32 lanes * 32 floats
    float* redL = (float*)(smc + 32768);
    if (khalf == 1) {
        float* dst = redO + (qblk * 32 + lane) * 32;
        #pragma unroll
        for (int nt = 0; nt < 8; ++nt)
            #pragma unroll
            for (int i = 0; i < 4; ++i) dst[nt * 4 + i] = oAcc[nt][i];
        redL[(qblk * 32 + lane) * 2 + 0] = l0sum;
        redL[(qblk * 32 + lane) * 2 + 1] = l1sum;
    }
    __syncthreads();
    if (khalf == 0) {
        const float* src = redO + (qblk * 32 + lane) * 32;
        const float inv0 = 1.0f / (l0sum + redL[(qblk * 32 + lane) * 2 + 0]);
        const float inv1 = 1.0f / (l1sum + redL[(qblk * 32 + lane) * 2 + 1]);
        const int qa = q0 + qblk * 16 + g;
        const int qb = qa + 8;
        #pragma unroll
        for (int nt = 0; nt < 8; ++nt) {
            const int c = nt * 8 + 2 * t;
            outg[(size_t)(64 + c) * HW + qa] = (oAcc[nt][0] + src[nt * 4 + 0]) * inv0;
            outg[(size_t)(65 + c) * HW + qa] = (oAcc[nt][1] + src[nt * 4 + 1]) * inv0;
            outg[(size_t)(64 + c) * HW + qb] = (oAcc[nt][2] + src[nt * 4 + 2]) * inv1;
            outg[(size_t)(65 + c) * HW + qb] = (oAcc[nt][3] + src[nt * 4 + 3]) * inv1;
        }
    }
}

extern "C" void kernel_launch(void* const* d_in, const int* in_sizes, int n_in,
                              void* d_out, int out_size)
{
    const float* content   = (const float*)d_in[0];
    const float* content_s = (const float*)d_in[1];
    const float* style     = (const float*)d_in[2];
    float* out = (float*)d_out;

    cudaFuncSetAttribute(sanet_main, cudaFuncAttributeMaxDynamicSharedMemorySize,
                         SMEM_BYTES);

    dim3 pgrid(NKT, 4);
    sanet_prepass<<<pgrid, 512>>>(content_s, style);

    dim3 grid(HW / BQ, 4);   // 128 CTAs
    sanet_main<<<grid, NT, SMEM_BYTES>>>(content, out);
}

// round 11
// speedup vs baseline: 1.0012x; 1.0012x over previous
#include <cuda_runtime.h>
#include <cuda_bf16.h>
#include <cstdint>

// SANet attention, warp-level bf16 HMMA (base PTX), R8:
// pre-pass kernel converts all K/V to bf16 hi/lo tile blocks in global scratch
// (exact SMEM layout); main kernel cp.asyncs finished tiles -> loop is
// GEMM1 / softmax / GEMM2 only. Math identical to R5 (3-term bf16 split,
// no-max softmax).

namespace {
constexpr int HW  = 4096;
constexpr int BQ  = 128;
constexpr int NKT = 32;
constexpr int NT  = 512;     // 16 warps: (qblk 0..7) x (khalf 0..1)

constexpr int QK_STR = 72;   // bf16 elems per K row (144 B)
constexpr int V_STR  = 136;  // bf16 elems per V row (272 B)

constexpr int KPLANE = 128 * 144;            // 18432 B per K plane
constexpr int VPLANE = 64 * 272;             // 17408 B per V plane
constexpr int OFF_VHI = 2 * KPLANE;          // V planes after K hi/lo
constexpr int BUF_SZ  = 2 * KPLANE + 2 * VPLANE;  // 71680 B per tile block
constexpr int SMEM_BYTES = 2 * BUF_SZ;       // 143360 B (double buffer)
constexpr int KLO_E = KPLANE / 2;            // elem offset hi->lo
constexpr int VLO_E = VPLANE / 2;
constexpr int NCHUNK = BUF_SZ / 16;          // 4480 16B chunks per tile
}

__device__ __align__(16) char g_kv[(size_t)4 * NKT * BUF_SZ];   // 9.2 MB scratch

__device__ __forceinline__ uint32_t smem_u32(const void* p) {
    uint32_t a;
    asm("{ .reg .u64 t; cvta.to.shared.u64 t, %1; cvt.u32.u64 %0, t; }"
        : "=r"(a) : "l"(p));
    return a;
}
__device__ __forceinline__ void cpa16(uint32_t s, const void* g) {
    asm volatile("cp.async.cg.shared.global [%0], [%1], 16;" :: "r"(s), "l"(g));
}
__device__ __forceinline__ void cpa_commit() {
    asm volatile("cp.async.commit_group;" ::: "memory");
}
__device__ __forceinline__ void cpa_wait0() {
    asm volatile("cp.async.wait_group 0;" ::: "memory");
}
__device__ __forceinline__ void ldsm4(uint32_t a, uint32_t* r) {
    asm volatile("ldmatrix.sync.aligned.m8n8.x4.shared.b16 {%0,%1,%2,%3}, [%4];"
                 : "=r"(r[0]), "=r"(r[1]), "=r"(r[2]), "=r"(r[3]) : "r"(a));
}
__device__ __forceinline__ void mma_bf16(float* d, const uint32_t* a,
                                         const uint32_t* b) {
    asm volatile(
        "mma.sync.aligned.m16n8k16.row.col.f32.bf16.bf16.f32 "
        "{%0,%1,%2,%3}, {%4,%5,%6,%7}, {%8,%9}, {%0,%1,%2,%3};"
        : "+f"(d[0]), "+f"(d[1]), "+f"(d[2]), "+f"(d[3])
        : "r"(a[0]), "r"(a[1]), "r"(a[2]), "r"(a[3]), "r"(b[0]), "r"(b[1]));
}
__device__ __forceinline__ void split_pack(float x, float y,
                                           uint32_t& hi, uint32_t& lo) {
    __nv_bfloat16 xh = __float2bfloat16_rn(x);
    __nv_bfloat16 yh = __float2bfloat16_rn(y);
    __nv_bfloat16 xl = __float2bfloat16_rn(x - __bfloat162float(xh));
    __nv_bfloat16 yl = __float2bfloat16_rn(y - __bfloat162float(yh));
    hi = (uint32_t)__bfloat16_as_ushort(xh) |
         ((uint32_t)__bfloat16_as_ushort(yh) << 16);
    lo = (uint32_t)__bfloat16_as_ushort(xl) |
         ((uint32_t)__bfloat16_as_ushort(yl) << 16);
}

// ---------------- pre-pass: K/V fp32 -> bf16 hi/lo tile blocks ----------------
__global__ __launch_bounds__(512)
void sanet_prepass(const float* __restrict__ Ksrc, const float* __restrict__ Vsrc)
{
    const int kt = blockIdx.x, b = blockIdx.y, tid = threadIdx.x;
    char* dst = g_kv + (size_t)(b * NKT + kt) * BUF_SZ;
    const float* Kg = Ksrc + (size_t)b * 64 * HW + kt * 128;
    const float* Vg = Vsrc + (size_t)b * 64 * HW + kt * 128;

    {   // K -> [k][c] planes (transpose), 144B rows
        const int k = tid & 127, c0 = (tid >> 7) * 16;
        float f[16];
        uint32_t h[8], l[8];
        #pragma unroll
        for (int j = 0; j < 16; ++j) f[j] = Kg[(size_t)(c0 + j) * HW + k];
        #pragma unroll
        for (int j = 0; j < 8; ++j) split_pack(f[2 * j], f[2 * j + 1], h[j], l[j]);
        char* d = dst + k * 144 + c0 * 2;
        *(uint4*)(d)                = make_uint4(h[0], h[1], h[2], h[3]);
        *(uint4*)(d + 16)           = make_uint4(h[4], h[5], h[6], h[7]);
        *(uint4*)(d + KPLANE)       = make_uint4(l[0], l[1], l[2], l[3]);
        *(uint4*)(d + KPLANE + 16)  = make_uint4(l[4], l[5], l[6], l[7]);
    }
    {   // V -> [c][k] planes (no transpose), 272B rows
        const int c = tid >> 3, kq = (tid & 7) * 16;
        float f[16];
        uint32_t h[8], l[8];
        #pragma unroll
        for (int j = 0; j < 4; ++j)
            *(float4*)(f + 4 * j) = *(const float4*)(Vg + (size_t)c * HW + kq + 4 * j);
        #pragma unroll
        for (int j = 0; j < 8; ++j) split_pack(f[2 * j], f[2 * j + 1], h[j], l[j]);
        char* d = dst + OFF_VHI + c * 272 + kq * 2;
        *(uint4*)(d)                = make_uint4(h[0], h[1], h[2], h[3]);
        *(uint4*)(d + 16)           = make_uint4(h[4], h[5], h[6], h[7]);
        *(uint4*)(d + VPLANE)       = make_uint4(l[0], l[1], l[2], l[3]);
        *(uint4*)(d + VPLANE + 16)  = make_uint4(l[4], l[5], l[6], l[7]);
    }
}

// ---------------- main kernel ----------------
__global__ __launch_bounds__(NT, 1)
void sanet_main(const float* __restrict__ content, float* __restrict__ out)
{
    extern __shared__ __align__(16) char smc[];
    const uint32_t sb = smem_u32(smc);

    const int tid   = threadIdx.x;
    const int wid   = tid >> 5;
    const int lane  = tid & 31;
    const int qblk  = wid & 7;
    const int khalf = wid >> 3;
    const int g     = lane >> 2;
    const int t     = lane & 3;
    const int b     = blockIdx.y;
    const int q0    = blockIdx.x * BQ;

    const float* Qg = content + (size_t)b * 64 * HW;
    float* outg     = out     + (size_t)b * 128 * HW;
    const char* kvb = g_kv + (size_t)b * NKT * BUF_SZ;

    const uint32_t laneK = (uint32_t)(lane & 7) * 144u +
                           (uint32_t)((lane >> 3) & 1) * 16u +
                           (uint32_t)((lane >> 4) & 1) * (uint32_t)KPLANE;
    const uint32_t laneV = (uint32_t)(lane & 7) * 272u +
                           (uint32_t)((lane >> 3) & 1) * 16u +
                           (uint32_t)((lane >> 4) & 1) * (uint32_t)VPLANE;

    // ---- prologue: stage Q fp32 into buf0 area ----
    float* stQ = (float*)smc;   // [64c][128q] fp32, 32 KB (before tile 0 load)
    #pragma unroll
    for (int j = 0; j < 4; ++j) {
        const int idx = tid + 512 * j;
        const int c = idx >> 5, kc = idx & 31;
        cpa16(sb + c * 512 + kc * 16, Qg + (size_t)c * HW + q0 + kc * 4);
    }
    cpa_commit();
    cpa_wait0();
    __syncthreads();

    {   // content passthrough (coalesced)
        const int q = tid & 127;
        const int c0 = (tid >> 7) * 16;
        #pragma unroll
        for (int j = 0; j < 16; ++j)
            outg[(size_t)(c0 + j) * HW + q0 + q] = stQ[(c0 + j) * 128 + q];
    }

    // ---- persistent Q A-fragments, split in registers from fp32 stage ----
    uint32_t qa_hi[4][4], qa_lo[4][4];
    {
        const int qA = qblk * 16 + g;
        #pragma unroll
        for (int s = 0; s < 4; ++s) {
            const int ch = 16 * s + 2 * t;
            split_pack(stQ[ch * 128 + qA],           stQ[(ch + 1) * 128 + qA],
                       qa_hi[s][0], qa_lo[s][0]);
            split_pack(stQ[ch * 128 + qA + 8],       stQ[(ch + 1) * 128 + qA + 8],
                       qa_hi[s][1], qa_lo[s][1]);
            split_pack(stQ[(ch + 8) * 128 + qA],     stQ[(ch + 9) * 128 + qA],
                       qa_hi[s][2], qa_lo[s][2]);
            split_pack(stQ[(ch + 8) * 128 + qA + 8], stQ[(ch + 9) * 128 + qA + 8],
                       qa_hi[s][3], qa_lo[s][3]);
        }
    }
    __syncthreads();   // stage reads done before tile 0 overwrites buf0

    // ---- prime tile 0 ----
    for (int j = tid; j < NCHUNK; j += NT)
        cpa16(sb + j * 16, kvb + j * 16);
    cpa_commit();
    cpa_wait0();
    __syncthreads();

    float oAcc[8][4];
    #pragma unroll
    for (int nt = 0; nt < 8; ++nt)
        #pragma unroll
        for (int i = 0; i < 4; ++i) oAcc[nt][i] = 0.0f;
    float l0sum = 0.0f, l1sum = 0.0f;

    for (int kt = 0; kt < NKT; ++kt) {
        // prefetch tile kt+1 into the other buffer (overlaps the GEMMs)
        if (kt + 1 < NKT) {
            const uint32_t dst = sb + (uint32_t)((kt + 1) & 1) * BUF_SZ;
            const char* src = kvb + (size_t)(kt + 1) * BUF_SZ;
            for (int j = tid; j < NCHUNK; j += NT)
                cpa16(dst + j * 16, src + j * 16);
            cpa_commit();
        }

        const uint32_t bufb = sb + (uint32_t)(kt & 1) * BUF_SZ;
        const uint32_t kaddr = bufb + (uint32_t)khalf * (64u * 144u) + laneK;
        const uint32_t vaddr = bufb + OFF_VHI + (uint32_t)khalf * 128u + laneV;

        // ---- GEMM1: S[16q x 64k] = Q.K^T (3-term bf16 split) ----
        float sAcc[8][4];
        #pragma unroll
        for (int nt = 0; nt < 8; ++nt)
            #pragma unroll
            for (int i = 0; i < 4; ++i) sAcc[nt][i] = 0.0f;

        #pragma unroll
        for (int s = 0; s < 4; ++s) {
            #pragma unroll
            for (int np = 0; np < 4; ++np) {
                uint32_t ra[4], rb[4];
                ldsm4(kaddr + (2 * np) * 1152u + s * 32u, ra);
                ldsm4(kaddr + (2 * np + 1) * 1152u + s * 32u, rb);
                mma_bf16(sAcc[2 * np],     qa_hi[s], ra);
                mma_bf16(sAcc[2 * np + 1], qa_hi[s], rb);
                mma_bf16(sAcc[2 * np],     qa_hi[s], ra + 2);
                mma_bf16(sAcc[2 * np + 1], qa_hi[s], rb + 2);
                mma_bf16(sAcc[2 * np],     qa_lo[s], ra);
                mma_bf16(sAcc[2 * np + 1], qa_lo[s], rb);
            }
        }

        // ---- softmax (no max shift) + in-place P fragment build ----
        float* flat = &sAcc[0][0];
        float r0 = 0.0f, r1 = 0.0f;
        #pragma unroll
        for (int s = 0; s < 4; ++s) {
            float p[8];
            #pragma unroll
            for (int i = 0; i < 8; ++i) p[i] = __expf(flat[8 * s + i]);
            r0 += (p[0] + p[1]) + (p[4] + p[5]);
            r1 += (p[2] + p[3]) + (p[6] + p[7]);
            uint32_t h01, l01, h23, l23, h45, l45, h67, l67;
            split_pack(p[0], p[1], h01, l01);
            split_pack(p[2], p[3], h23, l23);
            split_pack(p[4], p[5], h45, l45);
            split_pack(p[6], p[7], h67, l67);
            flat[8 * s + 0] = __uint_as_float(h01);
            flat[8 * s + 1] = __uint_as_float(h23);
            flat[8 * s + 2] = __uint_as_float(h45);
            flat[8 * s + 3] = __uint_as_float(h67);
            flat[8 * s + 4] = __uint_as_float(l01);
            flat[8 * s + 5] = __uint_as_float(l23);
            flat[8 * s + 6] = __uint_as_float(l45);
            flat[8 * s + 7] = __uint_as_float(l67);
        }
        r0 += __shfl_xor_sync(0xffffffffu, r0, 1);
        r0 += __shfl_xor_sync(0xffffffffu, r0, 2);
        r1 += __shfl_xor_sync(0xffffffffu, r1, 1);
        r1 += __shfl_xor_sync(0xffffffffu, r1, 2);
        l0sum += r0;
        l1sum += r1;

        // ---- GEMM2: O[16q x 64c] += P.V^T (partial over this key half) ----
        #pragma unroll
        for (int s = 0; s < 4; ++s) {
            uint32_t ah[4], al[4];
            #pragma unroll
            for (int i = 0; i < 4; ++i) {
                ah[i] = __float_as_uint(flat[8 * s + i]);
                al[i] = __float_as_uint(flat[8 * s + 4 + i]);
            }
            #pragma unroll
            for (int np = 0; np < 4; ++np) {
                uint32_t ra[4], rb[4];
                ldsm4(vaddr + (2 * np) * 2176u + s * 32u, ra);
                ldsm4(vaddr + (2 * np + 1) * 2176u + s * 32u, rb);
                mma_bf16(oAcc[2 * np],     ah, ra);
                mma_bf16(oAcc[2 * np + 1], ah, rb);
                mma_bf16(oAcc[2 * np],     ah, ra + 2);
                mma_bf16(oAcc[2 * np + 1], ah, rb + 2);
                mma_bf16(oAcc[2 * np],     al, ra);
                mma_bf16(oAcc[2 * np + 1], al, rb);
            }
        }

        if (kt + 1 < NKT) cpa_wait0();
        __syncthreads();   // all reads of buf[kt&1] done; tile kt+1 visible
    }

    // ---- epilogue: pair-reduce khalf partials via SMEM, normalize, store ----
    float* redO = (float*)smc;             // 8 warps * 32 lanes * 32 floats
    float* redL = (float*)(smc + 32768);
    if (khalf == 1) {
        float* dst = redO + (qblk * 32 + lane) * 32;
        #pragma unroll
        for (int nt = 0; nt < 8; ++nt)
            #pragma unroll
            for (int i = 0; i < 4; ++i) dst[nt * 4 + i] = oAcc[nt][i];
        redL[(qblk * 32 + lane) * 2 + 0] = l0sum;
        redL[(qblk * 32 + lane) * 2 + 1] = l1sum;
    }
    __syncthreads();
    if (khalf == 0) {
        const float* src = redO + (qblk * 32 + lane) * 32;
        const float inv0 = 1.0f / (l0sum + redL[(qblk * 32 + lane) * 2 + 0]);
        const float inv1 = 1.0f / (l1sum + redL[(qblk * 32 + lane) * 2 + 1]);
        const int qa = q0 + qblk * 16 + g;
        const int qb = qa + 8;
        #pragma unroll
        for (int nt = 0; nt < 8; ++nt) {
            const int c = nt * 8 + 2 * t;
            outg[(size_t)(64 + c) * HW + qa] = (oAcc[nt][0] + src[nt * 4 + 0]) * inv0;
            outg[(size_t)(65 + c) * HW + qa] = (oAcc[nt][1] + src[nt * 4 + 1]) * inv0;
            outg[(size_t)(64 + c) * HW + qb] = (oAcc[nt][2] + src[nt * 4 + 2]) * inv1;
            outg[(size_t)(65 + c) * HW + qb] = (oAcc[nt][3] + src[nt * 4 + 3]) * inv1;
        }
    }
}

extern "C" void kernel_launch(void* const* d_in, const int* in_sizes, int n_in,
                              void* d_out, int out_size)
{
    const float* content   = (const float*)d_in[0];
    const float* content_s = (const float*)d_in[1];
    const float* style     = (const float*)d_in[2];
    float* out = (float*)d_out;

    cudaFuncSetAttribute(sanet_main, cudaFuncAttributeMaxDynamicSharedMemorySize,
                         SMEM_BYTES);

    dim3 pgrid(NKT, 4);
    sanet_prepass<<<pgrid, 512>>>(content_s, style);

    dim3 grid(HW / BQ, 4);   // 128 CTAs
    sanet_main<<<grid, NT, SMEM_BYTES>>>(content, out);
}

// round 12
// speedup vs baseline: 1.0015x; 1.0002x over previous
#include <cuda_runtime.h>
#include <cuda_bf16.h>
#include <cstdint>

// SANet attention, warp-level bf16 HMMA (base PTX), R8:
// pre-pass kernel converts all K/V to bf16 hi/lo tile blocks in global scratch
// (exact SMEM layout); main kernel cp.asyncs finished tiles -> loop is
// GEMM1 / softmax / GEMM2 only. Math identical to R5 (3-term bf16 split,
// no-max softmax).

namespace {
constexpr int HW  = 4096;
constexpr int BQ  = 128;
constexpr int NKT = 32;
constexpr int NT  = 512;     // 16 warps: (qblk 0..7) x (khalf 0..1)

constexpr int QK_STR = 72;   // bf16 elems per K row (144 B)
constexpr int V_STR  = 136;  // bf16 elems per V row (272 B)

constexpr int KPLANE = 128 * 144;            // 18432 B per K plane
constexpr int VPLANE = 64 * 272;             // 17408 B per V plane
constexpr int OFF_VHI = 2 * KPLANE;          // V planes after K hi/lo
constexpr int BUF_SZ  = 2 * KPLANE + 2 * VPLANE;  // 71680 B per tile block
constexpr int SMEM_BYTES = 2 * BUF_SZ;       // 143360 B (double buffer)
constexpr int KLO_E = KPLANE / 2;            // elem offset hi->lo
constexpr int VLO_E = VPLANE / 2;
constexpr int NCHUNK = BUF_SZ / 16;          // 4480 16B chunks per tile
}

__device__ __align__(16) char g_kv[(size_t)4 * NKT * BUF_SZ];   // 9.2 MB scratch

__device__ __forceinline__ uint32_t smem_u32(const void* p) {
    uint32_t a;
    asm("{ .reg .u64 t; cvta.to.shared.u64 t, %1; cvt.u32.u64 %0, t; }"
        : "=r"(a) : "l"(p));
    return a;
}
__device__ __forceinline__ void cpa16(uint32_t s, const void* g) {
    asm volatile("cp.async.cg.shared.global [%0], [%1], 16;" :: "r"(s), "l"(g));
}
__device__ __forceinline__ void cpa_commit() {
    asm volatile("cp.async.commit_group;" ::: "memory");
}
__device__ __forceinline__ void cpa_wait0() {
    asm volatile("cp.async.wait_group 0;" ::: "memory");
}
__device__ __forceinline__ void ldsm4(uint32_t a, uint32_t* r) {
    asm volatile("ldmatrix.sync.aligned.m8n8.x4.shared.b16 {%0,%1,%2,%3}, [%4];"
                 : "=r"(r[0]), "=r"(r[1]), "=r"(r[2]), "=r"(r[3]) : "r"(a));
}
__device__ __forceinline__ void mma_bf16(float* d, const uint32_t* a,
                                         const uint32_t* b) {
    asm volatile(
        "mma.sync.aligned.m16n8k16.row.col.f32.bf16.bf16.f32 "
        "{%0,%1,%2,%3}, {%4,%5,%6,%7}, {%8,%9}, {%0,%1,%2,%3};"
        : "+f"(d[0]), "+f"(d[1]), "+f"(d[2]), "+f"(d[3])
        : "r"(a[0]), "r"(a[1]), "r"(a[2]), "r"(a[3]), "r"(b[0]), "r"(b[1]));
}
__device__ __forceinline__ void split_pack(float x, float y,
                                           uint32_t& hi, uint32_t& lo) {
    __nv_bfloat16 xh = __float2bfloat16_rn(x);
    __nv_bfloat16 yh = __float2bfloat16_rn(y);
    __nv_bfloat16 xl = __float2bfloat16_rn(x - __bfloat162float(xh));
    __nv_bfloat16 yl = __float2bfloat16_rn(y - __bfloat162float(yh));
    hi = (uint32_t)__bfloat16_as_ushort(xh) |
         ((uint32_t)__bfloat16_as_ushort(yh) << 16);
    lo = (uint32_t)__bfloat16_as_ushort(xl) |
         ((uint32_t)__bfloat16_as_ushort(yl) << 16);
}

// ---------------- pre-pass: K/V fp32 -> bf16 hi/lo tile blocks ----------------
__global__ __launch_bounds__(512)
void sanet_prepass(const float* __restrict__ Ksrc, const float* __restrict__ Vsrc)
{
    const int kt = blockIdx.x, b = blockIdx.y, tid = threadIdx.x;
    char* dst = g_kv + (size_t)(b * NKT + kt) * BUF_SZ;
    const float* Kg = Ksrc + (size_t)b * 64 * HW + kt * 128;
    const float* Vg = Vsrc + (size_t)b * 64 * HW + kt * 128;

    {   // K -> [k][c] planes (transpose), 144B rows
        const int k = tid & 127, c0 = (tid >> 7) * 16;
        float f[16];
        uint32_t h[8], l[8];
        #pragma unroll
        for (int j = 0; j < 16; ++j) f[j] = Kg[(size_t)(c0 + j) * HW + k];
        #pragma unroll
        for (int j = 0; j < 8; ++j) split_pack(f[2 * j], f[2 * j + 1], h[j], l[j]);
        char* d = dst + k * 144 + c0 * 2;
        *(uint4*)(d)                = make_uint4(h[0], h[1], h[2], h[3]);
        *(uint4*)(d + 16)           = make_uint4(h[4], h[5], h[6], h[7]);
        *(uint4*)(d + KPLANE)       = make_uint4(l[0], l[1], l[2], l[3]);
        *(uint4*)(d + KPLANE + 16)  = make_uint4(l[4], l[5], l[6], l[7]);
    }
    {   // V -> [c][k] planes (no transpose), 272B rows
        const int c = tid >> 3, kq = (tid & 7) * 16;
        float f[16];
        uint32_t h[8], l[8];
        #pragma unroll
        for (int j = 0; j < 4; ++j)
            *(float4*)(f + 4 * j) = *(const float4*)(Vg + (size_t)c * HW + kq + 4 * j);
        #pragma unroll
        for (int j = 0; j < 8; ++j) split_pack(f[2 * j], f[2 * j + 1], h[j], l[j]);
        char* d = dst + OFF_VHI + c * 272 + kq * 2;
        *(uint4*)(d)                = make_uint4(h[0], h[1], h[2], h[3]);
        *(uint4*)(d + 16)           = make_uint4(h[4], h[5], h[6], h[7]);
        *(uint4*)(d + VPLANE)       = make_uint4(l[0], l[1], l[2], l[3]);
        *(uint4*)(d + VPLANE + 16)  = make_uint4(l[4], l[5], l[6], l[7]);
    }
}

// ---------------- main kernel ----------------
__global__ __launch_bounds__(NT, 1)
void sanet_main(const float* __restrict__ content, float* __restrict__ out)
{
    extern __shared__ __align__(16) char smc[];
    const uint32_t sb = smem_u32(smc);

    const int tid   = threadIdx.x;
    const int wid   = tid >> 5;
    const int lane  = tid & 31;
    const int qblk  = wid & 7;
    const int khalf = wid >> 3;
    const int g     = lane >> 2;
    const int t     = lane & 3;
    const int b     = blockIdx.y;
    const int q0    = blockIdx.x * BQ;

    const float* Qg = content + (size_t)b * 64 * HW;
    float* outg     = out     + (size_t)b * 128 * HW;
    const char* kvb = g_kv + (size_t)b * NKT * BUF_SZ;

    const uint32_t laneK = (uint32_t)(lane & 7) * 144u +
                           (uint32_t)((lane >> 3) & 1) * 16u +
                           (uint32_t)((lane >> 4) & 1) * (uint32_t)KPLANE;
    const uint32_t laneV = (uint32_t)(lane & 7) * 272u +
                           (uint32_t)((lane >> 3) & 1) * 16u +
                           (uint32_t)((lane >> 4) & 1) * (uint32_t)VPLANE;

    // ---- prologue: stage Q fp32 into buf0 area ----
    float* stQ = (float*)smc;   // [64c][128q] fp32, 32 KB (before tile 0 load)
    #pragma unroll
    for (int j = 0; j < 4; ++j) {
        const int idx = tid + 512 * j;
        const int c = idx >> 5, kc = idx & 31;
        cpa16(sb + c * 512 + kc * 16, Qg + (size_t)c * HW + q0 + kc * 4);
    }
    cpa_commit();
    cpa_wait0();
    __syncthreads();

    {   // content passthrough (coalesced)
        const int q = tid & 127;
        const int c0 = (tid >> 7) * 16;
        #pragma unroll
        for (int j = 0; j < 16; ++j)
            outg[(size_t)(c0 + j) * HW + q0 + q] = stQ[(c0 + j) * 128 + q];
    }

    // ---- persistent Q A-fragments, split in registers from fp32 stage ----
    uint32_t qa_hi[4][4], qa_lo[4][4];
    {
        const int qA = qblk * 16 + g;
        #pragma unroll
        for (int s = 0; s < 4; ++s) {
            const int ch = 16 * s + 2 * t;
            split_pack(stQ[ch * 128 + qA],           stQ[(ch + 1) * 128 + qA],
                       qa_hi[s][0], qa_lo[s][0]);
            split_pack(stQ[ch * 128 + qA + 8],       stQ[(ch + 1) * 128 + qA + 8],
                       qa_hi[s][1], qa_lo[s][1]);
            split_pack(stQ[(ch + 8) * 128 + qA],     stQ[(ch + 9) * 128 + qA],
                       qa_hi[s][2], qa_lo[s][2]);
            split_pack(stQ[(ch + 8) * 128 + qA + 8], stQ[(ch + 9) * 128 + qA + 8],
                       qa_hi[s][3], qa_lo[s][3]);
        }
    }
    __syncthreads();   // stage reads done before tile 0 overwrites buf0

    // ---- prime tile 0 ----
    for (int j = tid; j < NCHUNK; j += NT)
        cpa16(sb + j * 16, kvb + j * 16);
    cpa_commit();
    cpa_wait0();
    __syncthreads();

    float oAcc[8][4];
    #pragma unroll
    for (int nt = 0; nt < 8; ++nt)
        #pragma unroll
        for (int i = 0; i < 4; ++i) oAcc[nt][i] = 0.0f;
    float l0sum = 0.0f, l1sum = 0.0f;

    for (int kt = 0; kt < NKT; ++kt) {
        // prefetch tile kt+1 into the other buffer (overlaps the GEMMs)
        if (kt + 1 < NKT) {
            const uint32_t dst = sb + (uint32_t)((kt + 1) & 1) * BUF_SZ;
            const char* src = kvb + (size_t)(kt + 1) * BUF_SZ;
            for (int j = tid; j < NCHUNK; j += NT)
                cpa16(dst + j * 16, src + j * 16);
            cpa_commit();
        }

        const uint32_t bufb = sb + (uint32_t)(kt & 1) * BUF_SZ;
        const uint32_t kaddr = bufb + (uint32_t)khalf * (64u * 144u) + laneK;
        const uint32_t vaddr = bufb + OFF_VHI + (uint32_t)khalf * 128u + laneV;

        // ---- GEMM1: S[16q x 64k] = Q.K^T (3-term bf16 split) ----
        float sAcc[8][4];
        #pragma unroll
        for (int nt = 0; nt < 8; ++nt)
            #pragma unroll
            for (int i = 0; i < 4; ++i) sAcc[nt][i] = 0.0f;

        #pragma unroll
        for (int s = 0; s < 4; ++s) {
            #pragma unroll
            for (int np = 0; np < 4; ++np) {
                uint32_t ra[4], rb[4];
                ldsm4(kaddr + (2 * np) * 1152u + s * 32u, ra);
                ldsm4(kaddr + (2 * np + 1) * 1152u + s * 32u, rb);
                mma_bf16(sAcc[2 * np],     qa_hi[s], ra);
                mma_bf16(sAcc[2 * np + 1], qa_hi[s], rb);
                mma_bf16(sAcc[2 * np],     qa_hi[s], ra + 2);
                mma_bf16(sAcc[2 * np + 1], qa_hi[s], rb + 2);
                mma_bf16(sAcc[2 * np],     qa_lo[s], ra);
                mma_bf16(sAcc[2 * np + 1], qa_lo[s], rb);
            }
        }

        // ---- softmax (no max shift) + in-place P fragment build ----
        float* flat = &sAcc[0][0];
        float r0 = 0.0f, r1 = 0.0f;
        #pragma unroll
        for (int s = 0; s < 4; ++s) {
            float p[8];
            #pragma unroll
            for (int i = 0; i < 8; ++i) p[i] = __expf(flat[8 * s + i]);
            r0 += (p[0] + p[1]) + (p[4] + p[5]);
            r1 += (p[2] + p[3]) + (p[6] + p[7]);
            uint32_t h01, l01, h23, l23, h45, l45, h67, l67;
            split_pack(p[0], p[1], h01, l01);
            split_pack(p[2], p[3], h23, l23);
            split_pack(p[4], p[5], h45, l45);
            split_pack(p[6], p[7], h67, l67);
            flat[8 * s + 0] = __uint_as_float(h01);
            flat[8 * s + 1] = __uint_as_float(h23);
            flat[8 * s + 2] = __uint_as_float(h45);
            flat[8 * s + 3] = __uint_as_float(h67);
            flat[8 * s + 4] = __uint_as_float(l01);
            flat[8 * s + 5] = __uint_as_float(l23);
            flat[8 * s + 6] = __uint_as_float(l45);
            flat[8 * s + 7] = __uint_as_float(l67);
        }
        r0 += __shfl_xor_sync(0xffffffffu, r0, 1);
        r0 += __shfl_xor_sync(0xffffffffu, r0, 2);
        r1 += __shfl_xor_sync(0xffffffffu, r1, 1);
        r1 += __shfl_xor_sync(0xffffffffu, r1, 2);
        l0sum += r0;
        l1sum += r1;

        // ---- GEMM2: O[16q x 64c] += P.V^T (partial over this key half) ----
        #pragma unroll
        for (int s = 0; s < 4; ++s) {
            uint32_t ah[4], al[4];
            #pragma unroll
            for (int i = 0; i < 4; ++i) {
                ah[i] = __float_as_uint(flat[8 * s + i]);
                al[i] = __float_as_uint(flat[8 * s + 4 + i]);
            }
            #pragma unroll
            for (int np = 0; np < 4; ++np) {
                uint32_t ra[4], rb[4];
                ldsm4(vaddr + (2 * np) * 2176u + s * 32u, ra);
                ldsm4(vaddr + (2 * np + 1) * 2176u + s * 32u, rb);
                mma_bf16(oAcc[2 * np],     ah, ra);
                mma_bf16(oAcc[2 * np + 1], ah, rb);
                mma_bf16(oAcc[2 * np],     ah, ra + 2);
                mma_bf16(oAcc[2 * np + 1], ah, rb + 2);
                mma_bf16(oAcc[2 * np],     al, ra);
                mma_bf16(oAcc[2 * np + 1], al, rb);
            }
        }

        if (kt + 1 < NKT) cpa_wait0();
        __syncthreads();   // all reads of buf[kt&1] done; tile kt+1 visible
    }

    // ---- epilogue: pair-reduce khalf partials via SMEM, normalize, store ----
    float* redO = (float*)smc;             // 8 warps * 32 lanes * 32 floats
    float* redL = (float*)(smc + 32768);
    if (khalf == 1) {
        float* dst = redO + (qblk * 32 + lane) * 32;
        #pragma unroll
        for (int nt = 0; nt < 8; ++nt)
            #pragma unroll
            for (int i = 0; i < 4; ++i) dst[nt * 4 + i] = oAcc[nt][i];
        redL[(qblk * 32 + lane) * 2 + 0] = l0sum;
        redL[(qblk * 32 + lane) * 2 + 1] = l1sum;
    }
    __syncthreads();
    if (khalf == 0) {
        const float* src = redO + (qblk * 32 + lane) * 32;
        const float inv0 = 1.0f / (l0sum + redL[(qblk * 32 + lane) * 2 + 0]);
        const float inv1 = 1.0f / (l1sum + redL[(qblk * 32 + lane) * 2 + 1]);
        const int qa = q0 + qblk * 16 + g;
        const int qb = qa + 8;
        #pragma unroll
        for (int nt = 0; nt < 8; ++nt) {
            const int c = nt * 8 + 2 * t;
            outg[(size_t)(64 + c) * HW + qa] = (oAcc[nt][0] + src[nt * 4 + 0]) * inv0;
            outg[(size_t)(65 + c) * HW + qa] = (oAcc[nt][1] + src[nt * 4 + 1]) * inv0;
            outg[(size_t)(64 + c) * HW + qb] = (oAcc[nt][2] + src[nt * 4 + 2]) * inv1;
            outg[(size_t)(65 + c) * HW + qb] = (oAcc[nt][3] + src[nt * 4 + 3]) * inv1;
        }
    }
}

extern "C" void kernel_launch(void* const* d_in, const int* in_sizes, int n_in,
                              void* d_out, int out_size)
{
    const float* content   = (const float*)d_in[0];
    const float* content_s = (const float*)d_in[1];
    const float* style     = (const float*)d_in[2];
    float* out = (float*)d_out;

    cudaFuncSetAttribute(sanet_main, cudaFuncAttributeMaxDynamicSharedMemorySize,
                         SMEM_BYTES);

    dim3 pgrid(NKT, 4);
    sanet_prepass<<<pgrid, 512>>>(content_s, style);

    dim3 grid(HW / BQ, 4);   // 128 CTAs
    sanet_main<<<grid, NT, SMEM_BYTES>>>(content, out);
}

// round 13
// speedup vs baseline: 1.0042x; 1.0027x over previous
#include <cuda_runtime.h>
#include <cuda_bf16.h>
#include <cstdint>

// SANet attention, warp-level bf16 HMMA (base PTX), R8:
// pre-pass kernel converts all K/V to bf16 hi/lo tile blocks in global scratch
// (exact SMEM layout); main kernel cp.asyncs finished tiles -> loop is
// GEMM1 / softmax / GEMM2 only. Math identical to R5 (3-term bf16 split,
// no-max softmax).

namespace {
constexpr int HW  = 4096;
constexpr int BQ  = 128;
constexpr int NKT = 32;
constexpr int NT  = 512;     // 16 warps: (qblk 0..7) x (khalf 0..1)

constexpr int QK_STR = 72;   // bf16 elems per K row (144 B)
constexpr int V_STR  = 136;  // bf16 elems per V row (272 B)

constexpr int KPLANE = 128 * 144;            // 18432 B per K plane
constexpr int VPLANE = 64 * 272;             // 17408 B per V plane
constexpr int OFF_VHI = 2 * KPLANE;          // V planes after K hi/lo
constexpr int BUF_SZ  = 2 * KPLANE + 2 * VPLANE;  // 71680 B per tile block
constexpr int SMEM_BYTES = 2 * BUF_SZ;       // 143360 B (double buffer)
constexpr int KLO_E = KPLANE / 2;            // elem offset hi->lo
constexpr int VLO_E = VPLANE / 2;
constexpr int NCHUNK = BUF_SZ / 16;          // 4480 16B chunks per tile
}

__device__ __align__(16) char g_kv[(size_t)4 * NKT * BUF_SZ];   // 9.2 MB scratch

__device__ __forceinline__ uint32_t smem_u32(const void* p) {
    uint32_t a;
    asm("{ .reg .u64 t; cvta.to.shared.u64 t, %1; cvt.u32.u64 %0, t; }"
        : "=r"(a) : "l"(p));
    return a;
}
__device__ __forceinline__ void cpa16(uint32_t s, const void* g) {
    asm volatile("cp.async.cg.shared.global [%0], [%1], 16;" :: "r"(s), "l"(g));
}
__device__ __forceinline__ void cpa_commit() {
    asm volatile("cp.async.commit_group;" ::: "memory");
}
__device__ __forceinline__ void cpa_wait0() {
    asm volatile("cp.async.wait_group 0;" ::: "memory");
}
__device__ __forceinline__ void ldsm4(uint32_t a, uint32_t* r) {
    asm volatile("ldmatrix.sync.aligned.m8n8.x4.shared.b16 {%0,%1,%2,%3}, [%4];"
                 : "=r"(r[0]), "=r"(r[1]), "=r"(r[2]), "=r"(r[3]) : "r"(a));
}
__device__ __forceinline__ void mma_bf16(float* d, const uint32_t* a,
                                         const uint32_t* b) {
    asm volatile(
        "mma.sync.aligned.m16n8k16.row.col.f32.bf16.bf16.f32 "
        "{%0,%1,%2,%3}, {%4,%5,%6,%7}, {%8,%9}, {%0,%1,%2,%3};"
        : "+f"(d[0]), "+f"(d[1]), "+f"(d[2]), "+f"(d[3])
        : "r"(a[0]), "r"(a[1]), "r"(a[2]), "r"(a[3]), "r"(b[0]), "r"(b[1]));
}
__device__ __forceinline__ void split_pack(float x, float y,
                                           uint32_t& hi, uint32_t& lo) {
    __nv_bfloat16 xh = __float2bfloat16_rn(x);
    __nv_bfloat16 yh = __float2bfloat16_rn(y);
    __nv_bfloat16 xl = __float2bfloat16_rn(x - __bfloat162float(xh));
    __nv_bfloat16 yl = __float2bfloat16_rn(y - __bfloat162float(yh));
    hi = (uint32_t)__bfloat16_as_ushort(xh) |
         ((uint32_t)__bfloat16_as_ushort(yh) << 16);
    lo = (uint32_t)__bfloat16_as_ushort(xl) |
         ((uint32_t)__bfloat16_as_ushort(yl) << 16);
}

// ---------------- pre-pass: K/V fp32 -> bf16 hi/lo tile blocks ----------------
__global__ __launch_bounds__(512)
void sanet_prepass(const float* __restrict__ Ksrc, const float* __restrict__ Vsrc)
{
    const int kt = blockIdx.x, b = blockIdx.y, tid = threadIdx.x;
    char* dst = g_kv + (size_t)(b * NKT + kt) * BUF_SZ;
    const float* Kg = Ksrc + (size_t)b * 64 * HW + kt * 128;
    const float* Vg = Vsrc + (size_t)b * 64 * HW + kt * 128;

    {   // K -> [k][c] planes (transpose), 144B rows
        const int k = tid & 127, c0 = (tid >> 7) * 16;
        float f[16];
        uint32_t h[8], l[8];
        #pragma unroll
        for (int j = 0; j < 16; ++j) f[j] = Kg[(size_t)(c0 + j) * HW + k];
        #pragma unroll
        for (int j = 0; j < 8; ++j) split_pack(f[2 * j], f[2 * j + 1], h[j], l[j]);
        char* d = dst + k * 144 + c0 * 2;
        *(uint4*)(d)                = make_uint4(h[0], h[1], h[2], h[3]);
        *(uint4*)(d + 16)           = make_uint4(h[4], h[5], h[6], h[7]);
        *(uint4*)(d + KPLANE)       = make_uint4(l[0], l[1], l[2], l[3]);
        *(uint4*)(d + KPLANE + 16)  = make_uint4(l[4], l[5], l[6], l[7]);
    }
    {   // V -> [c][k] planes (no transpose), 272B rows
        const int c = tid >> 3, kq = (tid & 7) * 16;
        float f[16];
        uint32_t h[8], l[8];
        #pragma unroll
        for (int j = 0; j < 4; ++j)
            *(float4*)(f + 4 * j) = *(const float4*)(Vg + (size_t)c * HW + kq + 4 * j);
        #pragma unroll
        for (int j = 0; j < 8; ++j) split_pack(f[2 * j], f[2 * j + 1], h[j], l[j]);
        char* d = dst + OFF_VHI + c * 272 + kq * 2;
        *(uint4*)(d)                = make_uint4(h[0], h[1], h[2], h[3]);
        *(uint4*)(d + 16)           = make_uint4(h[4], h[5], h[6], h[7]);
        *(uint4*)(d + VPLANE)       = make_uint4(l[0], l[1], l[2], l[3]);
        *(uint4*)(d + VPLANE + 16)  = make_uint4(l[4], l[5], l[6], l[7]);
    }
}

// ---------------- main kernel ----------------
__global__ __launch_bounds__(NT, 1)
void sanet_main(const float* __restrict__ content, float* __restrict__ out)
{
    extern __shared__ __align__(16) char smc[];
    const uint32_t sb = smem_u32(smc);

    const int tid   = threadIdx.x;
    const int wid   = tid >> 5;
    const int lane  = tid & 31;
    const int qblk  = wid & 7;
    const int khalf = wid >> 3;
    const int g     = lane >> 2;
    const int t     = lane & 3;
    const int b     = blockIdx.y;
    const int q0    = blockIdx.x * BQ;

    const float* Qg = content + (size_t)b * 64 * HW;
    float* outg     = out     + (size_t)b * 128 * HW;
    const char* kvb = g_kv + (size_t)b * NKT * BUF_SZ;

    const uint32_t laneK = (uint32_t)(lane & 7) * 144u +
                           (uint32_t)((lane >> 3) & 1) * 16u +
                           (uint32_t)((lane >> 4) & 1) * (uint32_t)KPLANE;
    const uint32_t laneV = (uint32_t)(lane & 7) * 272u +
                           (uint32_t)((lane >> 3) & 1) * 16u +
                           (uint32_t)((lane >> 4) & 1) * (uint32_t)VPLANE;

    // ---- prologue: stage Q fp32 into buf0 area ----
    float* stQ = (float*)smc;   // [64c][128q] fp32, 32 KB (before tile 0 load)
    #pragma unroll
    for (int j = 0; j < 4; ++j) {
        const int idx = tid + 512 * j;
        const int c = idx >> 5, kc = idx & 31;
        cpa16(sb + c * 512 + kc * 16, Qg + (size_t)c * HW + q0 + kc * 4);
    }
    cpa_commit();
    cpa_wait0();
    __syncthreads();

    {   // content passthrough (coalesced)
        const int q = tid & 127;
        const int c0 = (tid >> 7) * 16;
        #pragma unroll
        for (int j = 0; j < 16; ++j)
            outg[(size_t)(c0 + j) * HW + q0 + q] = stQ[(c0 + j) * 128 + q];
    }

    // ---- persistent Q A-fragments, split in registers from fp32 stage ----
    uint32_t qa_hi[4][4], qa_lo[4][4];
    {
        const int qA = qblk * 16 + g;
        #pragma unroll
        for (int s = 0; s < 4; ++s) {
            const int ch = 16 * s + 2 * t;
            split_pack(stQ[ch * 128 + qA],           stQ[(ch + 1) * 128 + qA],
                       qa_hi[s][0], qa_lo[s][0]);
            split_pack(stQ[ch * 128 + qA + 8],       stQ[(ch + 1) * 128 + qA + 8],
                       qa_hi[s][1], qa_lo[s][1]);
            split_pack(stQ[(ch + 8) * 128 + qA],     stQ[(ch + 9) * 128 + qA],
                       qa_hi[s][2], qa_lo[s][2]);
            split_pack(stQ[(ch + 8) * 128 + qA + 8], stQ[(ch + 9) * 128 + qA + 8],
                       qa_hi[s][3], qa_lo[s][3]);
        }
    }
    __syncthreads();   // stage reads done before tile 0 overwrites buf0

    // ---- prime tile 0 ----
    for (int j = tid; j < NCHUNK; j += NT)
        cpa16(sb + j * 16, kvb + j * 16);
    cpa_commit();
    cpa_wait0();
    __syncthreads();

    float oAcc[8][4];
    #pragma unroll
    for (int nt = 0; nt < 8; ++nt)
        #pragma unroll
        for (int i = 0; i < 4; ++i) oAcc[nt][i] = 0.0f;
    float l0sum = 0.0f, l1sum = 0.0f;

    for (int kt = 0; kt < NKT; ++kt) {
        // prefetch tile kt+1 into the other buffer (overlaps the GEMMs)
        if (kt + 1 < NKT) {
            const uint32_t dst = sb + (uint32_t)((kt + 1) & 1) * BUF_SZ;
            const char* src = kvb + (size_t)(kt + 1) * BUF_SZ;
            for (int j = tid; j < NCHUNK; j += NT)
                cpa16(dst + j * 16, src + j * 16);
            cpa_commit();
        }

        const uint32_t bufb = sb + (uint32_t)(kt & 1) * BUF_SZ;
        const uint32_t kaddr = bufb + (uint32_t)khalf * (64u * 144u) + laneK;
        const uint32_t vaddr = bufb + OFF_VHI + (uint32_t)khalf * 128u + laneV;

        // ---- GEMM1: S[16q x 64k] = Q.K^T (3-term bf16 split) ----
        float sAcc[8][4];
        #pragma unroll
        for (int nt = 0; nt < 8; ++nt)
            #pragma unroll
            for (int i = 0; i < 4; ++i) sAcc[nt][i] = 0.0f;

        #pragma unroll
        for (int s = 0; s < 4; ++s) {
            #pragma unroll
            for (int np = 0; np < 4; ++np) {
                uint32_t ra[4], rb[4];
                ldsm4(kaddr + (2 * np) * 1152u + s * 32u, ra);
                ldsm4(kaddr + (2 * np + 1) * 1152u + s * 32u, rb);
                mma_bf16(sAcc[2 * np],     qa_hi[s], ra);
                mma_bf16(sAcc[2 * np + 1], qa_hi[s], rb);
                mma_bf16(sAcc[2 * np],     qa_hi[s], ra + 2);
                mma_bf16(sAcc[2 * np + 1], qa_hi[s], rb + 2);
                mma_bf16(sAcc[2 * np],     qa_lo[s], ra);
                mma_bf16(sAcc[2 * np + 1], qa_lo[s], rb);
            }
        }

        // ---- softmax (no max shift) + in-place P fragment build ----
        float* flat = &sAcc[0][0];
        float r0 = 0.0f, r1 = 0.0f;
        #pragma unroll
        for (int s = 0; s < 4; ++s) {
            float p[8];
            #pragma unroll
            for (int i = 0; i < 8; ++i) p[i] = __expf(flat[8 * s + i]);
            r0 += (p[0] + p[1]) + (p[4] + p[5]);
            r1 += (p[2] + p[3]) + (p[6] + p[7]);
            uint32_t h01, l01, h23, l23, h45, l45, h67, l67;
            split_pack(p[0], p[1], h01, l01);
            split_pack(p[2], p[3], h23, l23);
            split_pack(p[4], p[5], h45, l45);
            split_pack(p[6], p[7], h67, l67);
            flat[8 * s + 0] = __uint_as_float(h01);
            flat[8 * s + 1] = __uint_as_float(h23);
            flat[8 * s + 2] = __uint_as_float(h45);
            flat[8 * s + 3] = __uint_as_float(h67);
            flat[8 * s + 4] = __uint_as_float(l01);
            flat[8 * s + 5] = __uint_as_float(l23);
            flat[8 * s + 6] = __uint_as_float(l45);
            flat[8 * s + 7] = __uint_as_float(l67);
        }
        r0 += __shfl_xor_sync(0xffffffffu, r0, 1);
        r0 += __shfl_xor_sync(0xffffffffu, r0, 2);
        r1 += __shfl_xor_sync(0xffffffffu, r1, 1);
        r1 += __shfl_xor_sync(0xffffffffu, r1, 2);
        l0sum += r0;
        l1sum += r1;

        // ---- GEMM2: O[16q x 64c] += P.V^T (partial over this key half) ----
        #pragma unroll
        for (int s = 0; s < 4; ++s) {
            uint32_t ah[4], al[4];
            #pragma unroll
            for (int i = 0; i < 4; ++i) {
                ah[i] = __float_as_uint(flat[8 * s + i]);
                al[i] = __float_as_uint(flat[8 * s + 4 + i]);
            }
            #pragma unroll
            for (int np = 0; np < 4; ++np) {
                uint32_t ra[4], rb[4];
                ldsm4(vaddr + (2 * np) * 2176u + s * 32u, ra);
                ldsm4(vaddr + (2 * np + 1) * 2176u + s * 32u, rb);
                mma_bf16(oAcc[2 * np],     ah, ra);
                mma_bf16(oAcc[2 * np + 1], ah, rb);
                mma_bf16(oAcc[2 * np],     ah, ra + 2);
                mma_bf16(oAcc[2 * np + 1], ah, rb + 2);
                mma_bf16(oAcc[2 * np],     al, ra);
                mma_bf16(oAcc[2 * np + 1], al, rb);
            }
        }

        if (kt + 1 < NKT) cpa_wait0();
        __syncthreads();   // all reads of buf[kt&1] done; tile kt+1 visible
    }

    // ---- epilogue: pair-reduce khalf partials via SMEM, normalize, store ----
    float* redO = (float*)smc;             // 8 warps * 32 lanes * 32 floats
    float* redL = (float*)(smc + 32768);
    if (khalf == 1) {
        float* dst = redO + (qblk * 32 + lane) * 32;
        #pragma unroll
        for (int nt = 0; nt < 8; ++nt)
            #pragma unroll
            for (int i = 0; i < 4; ++i) dst[nt * 4 + i] = oAcc[nt][i];
        redL[(qblk * 32 + lane) * 2 + 0] = l0sum;
        redL[(qblk * 32 + lane) * 2 + 1] = l1sum;
    }
    __syncthreads();
    if (khalf == 0) {
        const float* src = redO + (qblk * 32 + lane) * 32;
        const float inv0 = 1.0f / (l0sum + redL[(qblk * 32 + lane) * 2 + 0]);
        const float inv1 = 1.0f / (l1sum + redL[(qblk * 32 + lane) * 2 + 1]);
        const int qa = q0 + qblk * 16 + g;
        const int qb = qa + 8;
        #pragma unroll
        for (int nt = 0; nt < 8; ++nt) {
            const int c = nt * 8 + 2 * t;
            outg[(size_t)(64 + c) * HW + qa] = (oAcc[nt][0] + src[nt * 4 + 0]) * inv0;
            outg[(size_t)(65 + c) * HW + qa] = (oAcc[nt][1] + src[nt * 4 + 1]) * inv0;
            outg[(size_t)(64 + c) * HW + qb] = (oAcc[nt][2] + src[nt * 4 + 2]) * inv1;
            outg[(size_t)(65 + c) * HW + qb] = (oAcc[nt][3] + src[nt * 4 + 3]) * inv1;
        }
    }
}

extern "C" void kernel_launch(void* const* d_in, const int* in_sizes, int n_in,
                              void* d_out, int out_size)
{
    const float* content   = (const float*)d_in[0];
    const float* content_s = (const float*)d_in[1];
    const float* style     = (const float*)d_in[2];
    float* out = (float*)d_out;

    cudaFuncSetAttribute(sanet_main, cudaFuncAttributeMaxDynamicSharedMemorySize,
                         SMEM_BYTES);

    dim3 pgrid(NKT, 4);
    sanet_prepass<<<pgrid, 512>>>(content_s, style);

    dim3 grid(HW / BQ, 4);   // 128 CTAs
    sanet_main<<<grid, NT, SMEM_BYTES>>>(content, out);
}